// round 2
// baseline (speedup 1.0000x reference)
#include <cuda_runtime.h>
#include <mma.h>

using namespace nvcuda;

#define MAXN 50000
#define MAXE 800000
#define MAXET (MAXN + MAXE)

// ---------------- scratch (device globals; no allocation allowed) ----------
__device__ float g_xl[MAXN * 128];     // source transform  [N,128]
__device__ float g_xr[MAXN * 128];     // target transform  [N,128]
__device__ float g_h [MAXN * 128];     // layer output accumulator / next act
__device__ float g_p [MAXET * 8];      // per-edge exp(score) [Etot,H]
__device__ float g_d [MAXN * 8];       // segment denom  [N,H]

// ---------------- fused dual GEMM: xl = A@Wl, xr = A@Wr (tf32 x3) ----------
// block: 256 threads = 8 warps. Block tile: 64 rows x 128 cols x {Wl,Wr}.
// warp w: row tile (w>>1), output select (w&1). 8 col tiles of 16 per warp.
// Split-precision: a = ab + as (tf32 parts); a*b ~= ab*bb + ab*bs + as*bb.
using frag_a = wmma::fragment<wmma::matrix_a, 16, 16, 8, wmma::precision::tf32, wmma::row_major>;
using frag_b = wmma::fragment<wmma::matrix_b, 16, 16, 8, wmma::precision::tf32, wmma::row_major>;
using frag_c = wmma::fragment<wmma::accumulator, 16, 16, 8, float>;

__global__ void dual_gemm(const float* __restrict__ Aext,
                          const float* __restrict__ Wl,
                          const float* __restrict__ Wr,
                          int useH, int n) {
    const float* A = useH ? g_h : Aext;
    int warp = threadIdx.x >> 5;
    int row0 = (blockIdx.x * 4 + (warp >> 1)) * 16;
    if (row0 >= n) return;                       // n % 16 == 0 for this dataset
    const float* W = (warp & 1) ? Wr : Wl;
    float*       C = (warp & 1) ? g_xr : g_xl;

    frag_c acc[8];
    #pragma unroll
    for (int i = 0; i < 8; ++i) wmma::fill_fragment(acc[i], 0.0f);

    for (int k = 0; k < 128; k += 8) {
        frag_a ab, as;
        wmma::load_matrix_sync(ab, A + (size_t)row0 * 128 + k, 128);
        #pragma unroll
        for (int i = 0; i < ab.num_elements; ++i) {
            float v = ab.x[i];
            float b = wmma::__float_to_tf32(v);
            as.x[i] = wmma::__float_to_tf32(v - b);
            ab.x[i] = b;
        }
        #pragma unroll
        for (int nt = 0; nt < 8; ++nt) {
            frag_b bb, bs;
            wmma::load_matrix_sync(bb, W + (size_t)k * 128 + nt * 16, 128);
            #pragma unroll
            for (int i = 0; i < bb.num_elements; ++i) {
                float v = bb.x[i];
                float b = wmma::__float_to_tf32(v);
                bs.x[i] = wmma::__float_to_tf32(v - b);
                bb.x[i] = b;
            }
            wmma::mma_sync(acc[nt], ab, bb, acc[nt]);
            wmma::mma_sync(acc[nt], ab, bs, acc[nt]);
            wmma::mma_sync(acc[nt], as, bb, acc[nt]);
        }
    }
    #pragma unroll
    for (int nt = 0; nt < 8; ++nt)
        wmma::store_matrix_sync(C + (size_t)row0 * 128 + nt * 16, acc[nt], 128,
                                wmma::mem_row_major);
}

// ---------------- per-layer init: h=0, d=0 ---------------------------------
__global__ void init_layer(int n) {
    int i = blockIdx.x * blockDim.x + threadIdx.x;
    if (i < n * 128) g_h[i] = 0.0f;
    if (i < n * 8)   g_d[i] = 0.0f;
}

// ---------------- edge score: warp per edge; exp fused, no max pass --------
// score[e,h] = sum_c att[h,c] * leaky_relu(xl[src,h,c] + xr[dst,h,c], 0.2)
// p = exp(score); atomic denom accumulate. (scores O(+-10) -> no overflow;
// the max factor cancels exactly in alpha.)
__global__ void edge_score(const int* __restrict__ ei,
                           const float* __restrict__ att,
                           int E, int etot) {
    int e = blockIdx.x * 8 + (threadIdx.x >> 5);
    if (e >= etot) return;
    int lane = threadIdx.x & 31;
    int s, d;
    if (e < E) { s = __ldg(&ei[e]); d = __ldg(&ei[E + e]); }
    else       { s = e - E; d = s; }

    float4 a4 = *(const float4*)&att[lane * 4];
    float4 l4 = *(const float4*)&g_xl[(size_t)s * 128 + lane * 4];
    float4 r4 = *(const float4*)&g_xr[(size_t)d * 128 + lane * 4];

    float v0 = l4.x + r4.x; v0 = v0 > 0.f ? v0 : 0.2f * v0;
    float v1 = l4.y + r4.y; v1 = v1 > 0.f ? v1 : 0.2f * v1;
    float v2 = l4.z + r4.z; v2 = v2 > 0.f ? v2 : 0.2f * v2;
    float v3 = l4.w + r4.w; v3 = v3 > 0.f ? v3 : 0.2f * v3;

    float part = v0 * a4.x + v1 * a4.y + v2 * a4.z + v3 * a4.w;
    part += __shfl_xor_sync(0xffffffffu, part, 1);
    part += __shfl_xor_sync(0xffffffffu, part, 2);

    if ((lane & 3) == 0) {
        int h = lane >> 2;
        float p = __expf(part);
        g_p[(size_t)e * 8 + h] = p;
        atomicAdd(&g_d[(size_t)d * 8 + h], p);
    }
}

// ---------------- aggregation: warp per edge, float4 atomics ---------------
__global__ void edge_aggr(const int* __restrict__ ei, int E, int etot) {
    int e = blockIdx.x * 8 + (threadIdx.x >> 5);
    if (e >= etot) return;
    int lane = threadIdx.x & 31;
    int s, d;
    if (e < E) { s = __ldg(&ei[e]); d = __ldg(&ei[E + e]); }
    else       { s = e - E; d = s; }
    int h = lane >> 2;
    float alpha = g_p[(size_t)e * 8 + h] / (g_d[(size_t)d * 8 + h] + 1e-16f);
    float4 l4 = *(const float4*)&g_xl[(size_t)s * 128 + lane * 4];
    float4 v  = make_float4(alpha * l4.x, alpha * l4.y, alpha * l4.z, alpha * l4.w);
    atomicAdd((float4*)&g_h[(size_t)d * 128 + lane * 4], v);
}

// ---------------- bias + relu (in place on g_h, feeds layer-2 gemm) --------
__global__ void bias_relu(const float* __restrict__ b, int n) {
    int i = blockIdx.x * blockDim.x + threadIdx.x;
    if (i >= n * 128) return;
    float v = g_h[i] + b[i & 127];
    g_h[i] = v > 0.f ? v : 0.f;
}

// ---------------- final fc: out = relu(g_h + b2) @ Wfc + bfc ---------------
__global__ void fc_out(const float* __restrict__ Wfc,
                       const float* __restrict__ bfc,
                       const float* __restrict__ b2,
                       float* __restrict__ out, int n) {
    __shared__ float Ws[128 * 10];
    __shared__ float bs[10];
    __shared__ float b2s[128];
    for (int i = threadIdx.x; i < 1280; i += blockDim.x) Ws[i] = Wfc[i];
    if (threadIdx.x < 10)  bs[threadIdx.x]  = bfc[threadIdx.x];
    if (threadIdx.x < 128) b2s[threadIdx.x] = b2[threadIdx.x];
    __syncthreads();
    int idx = blockIdx.x * blockDim.x + threadIdx.x;
    if (idx >= n * 10) return;
    int node = idx / 10;
    int c    = idx % 10;
    const float* hrow = &g_h[(size_t)node * 128];
    float acc = bs[c];
    #pragma unroll
    for (int k = 0; k < 128; ++k) {
        float hv = hrow[k] + b2s[k];
        hv = hv > 0.f ? hv : 0.f;
        acc += hv * Ws[k * 10 + c];
    }
    out[idx] = acc;
}

// ---------------- launch ---------------------------------------------------
extern "C" void kernel_launch(void* const* d_in, const int* in_sizes, int n_in,
                              void* d_out, int out_size) {
    const float* x    = (const float*)d_in[0];
    const int*   ei   = (const int*)  d_in[1];
    const float* Wl1  = (const float*)d_in[2];
    const float* Wr1  = (const float*)d_in[3];
    const float* att1 = (const float*)d_in[4];
    const float* b1   = (const float*)d_in[5];
    const float* Wl2  = (const float*)d_in[6];
    const float* Wr2  = (const float*)d_in[7];
    const float* att2 = (const float*)d_in[8];
    const float* b2   = (const float*)d_in[9];
    const float* Wfc  = (const float*)d_in[10];
    const float* bfc  = (const float*)d_in[11];
    float* out = (float*)d_out;

    int n    = in_sizes[0] / 128;
    int E    = in_sizes[1] / 2;
    int etot = E + n;

    int gemm_blocks = (n + 63) / 64;
    int ew_blocks   = (etot + 7) / 8;
    int node_blocks = (n * 128 + 255) / 256;
    int fc_blocks   = (n * 10 + 255) / 256;

    // ---- layer 1 ----
    dual_gemm<<<gemm_blocks, 256>>>(x, Wl1, Wr1, 0, n);     // -> g_xl, g_xr
    init_layer<<<node_blocks, 256>>>(n);
    edge_score<<<ew_blocks, 256>>>(ei, att1, E, etot);
    edge_aggr<<<ew_blocks, 256>>>(ei, E, etot);
    bias_relu<<<node_blocks, 256>>>(b1, n);

    // ---- layer 2 ----
    dual_gemm<<<gemm_blocks, 256>>>(nullptr, Wl2, Wr2, 1, n);
    init_layer<<<node_blocks, 256>>>(n);
    edge_score<<<ew_blocks, 256>>>(ei, att2, E, etot);
    edge_aggr<<<ew_blocks, 256>>>(ei, E, etot);

    // ---- fc (bias2 + relu fused) ----
    fc_out<<<fc_blocks, 256>>>(Wfc, bfc, b2, out, n);
}

// round 3
// speedup vs baseline: 2.6113x; 2.6113x over previous
#include <cuda_runtime.h>

#define MAXN 50000
#define MAXE 800000

// ---------------- scratch (device globals; no allocation allowed) ----------
__device__ float g_xl[MAXN * 128];     // source transform  [N,128]
__device__ float g_xr[MAXN * 128];     // target transform  [N,128]
__device__ float g_h [MAXN * 128];     // layer output / next activation
__device__ int   g_deg[MAXN];          // degree counts, then scatter cursors
__device__ int   g_rowptr[MAXN + 1];
__device__ int   g_blocksum[64];
__device__ int   g_csr_src[MAXE];      // src node per CSR slot (real edges only)

// ================= CSR build (by dst) ======================================
__global__ void deg_zero(int n) {
    int i = blockIdx.x * blockDim.x + threadIdx.x;
    if (i < n) g_deg[i] = 0;
}

__global__ void deg_count(const int* __restrict__ ei, int E) {
    int i = blockIdx.x * blockDim.x + threadIdx.x;
    if (i < E) atomicAdd(&g_deg[__ldg(&ei[E + i])], 1);
}

// block-level exclusive scan (1024/block) + per-block totals
__global__ void scan1(int n) {
    __shared__ int s[1024];
    int i = blockIdx.x * 1024 + threadIdx.x;
    int v = (i < n) ? g_deg[i] : 0;
    s[threadIdx.x] = v;
    __syncthreads();
    #pragma unroll
    for (int off = 1; off < 1024; off <<= 1) {
        int t = (threadIdx.x >= off) ? s[threadIdx.x - off] : 0;
        __syncthreads();
        s[threadIdx.x] += t;
        __syncthreads();
    }
    if (i < n) g_rowptr[i] = s[threadIdx.x] - v;           // exclusive
    if (threadIdx.x == 1023) g_blocksum[blockIdx.x] = s[1023];
}

__global__ void scan2(int nb) {                            // 1 thread: tiny
    if (threadIdx.x == 0) {
        int run = 0;
        for (int b = 0; b < nb; ++b) {
            int t = g_blocksum[b];
            g_blocksum[b] = run;
            run += t;
        }
    }
}

__global__ void scan3(int n, int E) {
    int i = blockIdx.x * blockDim.x + threadIdx.x;
    if (i < n) {
        g_rowptr[i] += g_blocksum[i >> 10];
        g_deg[i] = 0;                                      // reuse as cursor
    }
    if (i == 0) g_rowptr[n] = E;
}

__global__ void scatter(const int* __restrict__ ei, int E) {
    int i = blockIdx.x * blockDim.x + threadIdx.x;
    if (i >= E) return;
    int s = __ldg(&ei[i]);
    int d = __ldg(&ei[E + i]);
    int pos = g_rowptr[d] + atomicAdd(&g_deg[d], 1);
    g_csr_src[pos] = s;
}

// ================= GEMM: C[n,128] = A[n,128] @ W[128,128] ==================
// block: 256 threads, tile 32 rows x 128 cols, 4x4 register tile per thread
__global__ void gemm128(const float* __restrict__ Aext,
                        const float* __restrict__ W,
                        int useH, int dstSel, int n) {
    __shared__ float As[32][33];
    __shared__ float Ws[32][128];
    const float* A = useH ? g_h : Aext;
    float* C = (dstSel == 0) ? g_xl : g_xr;

    int tid  = threadIdx.x;
    int row0 = blockIdx.x * 32;
    int cg   = tid & 31;
    int rg   = tid >> 5;

    float acc[4][4] = {};

    for (int kk = 0; kk < 128; kk += 32) {
        {
            int r  = tid >> 3;
            int k4 = (tid & 7) * 4;
            float4 v = make_float4(0.f, 0.f, 0.f, 0.f);
            if (row0 + r < n)
                v = *(const float4*)&A[(size_t)(row0 + r) * 128 + kk + k4];
            As[r][k4 + 0] = v.x; As[r][k4 + 1] = v.y;
            As[r][k4 + 2] = v.z; As[r][k4 + 3] = v.w;
        }
        #pragma unroll
        for (int t = 0; t < 4; ++t) {
            int f = tid + t * 256;
            int k = f >> 5;
            int c = (f & 31) * 4;
            *(float4*)&Ws[k][c] = *(const float4*)&W[(size_t)(kk + k) * 128 + c];
        }
        __syncthreads();

        #pragma unroll
        for (int k = 0; k < 32; ++k) {
            float a0 = As[rg * 4 + 0][k];
            float a1 = As[rg * 4 + 1][k];
            float a2 = As[rg * 4 + 2][k];
            float a3 = As[rg * 4 + 3][k];
            float4 w = *(const float4*)&Ws[k][cg * 4];
            acc[0][0] += a0 * w.x; acc[0][1] += a0 * w.y; acc[0][2] += a0 * w.z; acc[0][3] += a0 * w.w;
            acc[1][0] += a1 * w.x; acc[1][1] += a1 * w.y; acc[1][2] += a1 * w.z; acc[1][3] += a1 * w.w;
            acc[2][0] += a2 * w.x; acc[2][1] += a2 * w.y; acc[2][2] += a2 * w.z; acc[2][3] += a2 * w.w;
            acc[3][0] += a3 * w.x; acc[3][1] += a3 * w.y; acc[3][2] += a3 * w.z; acc[3][3] += a3 * w.w;
        }
        __syncthreads();
    }

    #pragma unroll
    for (int i = 0; i < 4; ++i) {
        int r = row0 + rg * 4 + i;
        if (r < n)
            *(float4*)&C[(size_t)r * 128 + cg * 4] =
                make_float4(acc[i][0], acc[i][1], acc[i][2], acc[i][3]);
    }
}

// ================= fused GAT layer: warp per dst node ======================
// For node d: sweep incoming edges (CSR) + implicit self loop.
//   score[h] = att[h] . leaky_relu(xl[s] + xr[d]); p = exp(score)
//   h[d] = sum_e p_e * xl[s_e] / sum_e p_e   (+ optional bias, relu)
// No atomics; no max pass (scores are O(+-10), exp safe; max cancels in alpha).
__device__ __forceinline__ float edge_p(float4 l4, float4 r4, float4 a4) {
    float v0 = l4.x + r4.x; v0 = v0 > 0.f ? v0 : 0.2f * v0;
    float v1 = l4.y + r4.y; v1 = v1 > 0.f ? v1 : 0.2f * v1;
    float v2 = l4.z + r4.z; v2 = v2 > 0.f ? v2 : 0.2f * v2;
    float v3 = l4.w + r4.w; v3 = v3 > 0.f ? v3 : 0.2f * v3;
    float part = v0 * a4.x + v1 * a4.y + v2 * a4.z + v3 * a4.w;
    part += __shfl_xor_sync(0xffffffffu, part, 1);
    part += __shfl_xor_sync(0xffffffffu, part, 2);
    return __expf(part);        // same value in all 4 lanes of the head group
}

__global__ void gat_layer(const float* __restrict__ att,
                          const float* __restrict__ bias,
                          int doRelu, int n) {
    int d = blockIdx.x * 8 + (threadIdx.x >> 5);
    if (d >= n) return;
    int lane = threadIdx.x & 31;

    float4 a4 = *(const float4*)&att[lane * 4];
    float4 r4 = *(const float4*)&g_xr[(size_t)d * 128 + lane * 4];

    // self loop
    float4 l4 = *(const float4*)&g_xl[(size_t)d * 128 + lane * 4];
    float p = edge_p(l4, r4, a4);
    float4 acc = make_float4(p * l4.x, p * l4.y, p * l4.z, p * l4.w);
    float den = p;

    int e   = g_rowptr[d];
    int end = g_rowptr[d + 1];
    int snext = (e < end) ? g_csr_src[e] : 0;
    for (; e < end; ++e) {
        int s = snext;
        l4 = *(const float4*)&g_xl[(size_t)s * 128 + lane * 4];
        snext = (e + 1 < end) ? g_csr_src[e + 1] : 0;
        p = edge_p(l4, r4, a4);
        acc.x += p * l4.x; acc.y += p * l4.y;
        acc.z += p * l4.z; acc.w += p * l4.w;
        den += p;
    }

    float inv = 1.0f / (den + 1e-16f);
    float4 b4 = bias ? *(const float4*)&bias[lane * 4]
                     : make_float4(0.f, 0.f, 0.f, 0.f);
    float4 o;
    o.x = acc.x * inv + b4.x;
    o.y = acc.y * inv + b4.y;
    o.z = acc.z * inv + b4.z;
    o.w = acc.w * inv + b4.w;
    if (doRelu) {
        o.x = o.x > 0.f ? o.x : 0.f;
        o.y = o.y > 0.f ? o.y : 0.f;
        o.z = o.z > 0.f ? o.z : 0.f;
        o.w = o.w > 0.f ? o.w : 0.f;
    }
    *(float4*)&g_h[(size_t)d * 128 + lane * 4] = o;
}

// ================= final fc: out = relu(g_h + b2) @ Wfc + bfc ==============
__global__ void fc_out(const float* __restrict__ Wfc,
                       const float* __restrict__ bfc,
                       const float* __restrict__ b2,
                       float* __restrict__ out, int n) {
    __shared__ float Ws[128 * 10];
    __shared__ float bs[10];
    __shared__ float b2s[128];
    for (int i = threadIdx.x; i < 1280; i += blockDim.x) Ws[i] = Wfc[i];
    if (threadIdx.x < 10)  bs[threadIdx.x]  = bfc[threadIdx.x];
    if (threadIdx.x < 128) b2s[threadIdx.x] = b2[threadIdx.x];
    __syncthreads();
    int idx = blockIdx.x * blockDim.x + threadIdx.x;
    if (idx >= n * 10) return;
    int node = idx / 10;
    int c    = idx % 10;
    const float* hrow = &g_h[(size_t)node * 128];
    float acc = bs[c];
    #pragma unroll
    for (int k = 0; k < 128; ++k) {
        float hv = hrow[k] + b2s[k];
        hv = hv > 0.f ? hv : 0.f;
        acc += hv * Ws[k * 10 + c];
    }
    out[idx] = acc;
}

// ================= launch ==================================================
extern "C" void kernel_launch(void* const* d_in, const int* in_sizes, int n_in,
                              void* d_out, int out_size) {
    const float* x    = (const float*)d_in[0];
    const int*   ei   = (const int*)  d_in[1];
    const float* Wl1  = (const float*)d_in[2];
    const float* Wr1  = (const float*)d_in[3];
    const float* att1 = (const float*)d_in[4];
    const float* b1   = (const float*)d_in[5];
    const float* Wl2  = (const float*)d_in[6];
    const float* Wr2  = (const float*)d_in[7];
    const float* att2 = (const float*)d_in[8];
    const float* b2   = (const float*)d_in[9];
    const float* Wfc  = (const float*)d_in[10];
    const float* bfc  = (const float*)d_in[11];
    float* out = (float*)d_out;

    int n = in_sizes[0] / 128;
    int E = in_sizes[1] / 2;

    int nb_scan     = (n + 1023) / 1024;
    int gemm_blocks = (n + 31) / 32;
    int gat_blocks  = (n + 7) / 8;
    int fc_blocks   = (n * 10 + 255) / 256;
    int e_blocks    = (E + 255) / 256;
    int n_blocks    = (n + 255) / 256;

    // ---- CSR build (reused by both layers) ----
    deg_zero<<<n_blocks, 256>>>(n);
    deg_count<<<e_blocks, 256>>>(ei, E);
    scan1<<<nb_scan, 1024>>>(n);
    scan2<<<1, 32>>>(nb_scan);
    scan3<<<n_blocks, 256>>>(n, E);
    scatter<<<e_blocks, 256>>>(ei, E);

    // ---- layer 1 ----
    gemm128<<<gemm_blocks, 256>>>(x, Wl1, 0, 0, n);
    gemm128<<<gemm_blocks, 256>>>(x, Wr1, 0, 1, n);
    gat_layer<<<gat_blocks, 256>>>(att1, b1, 1, n);   // bias + relu fused

    // ---- layer 2 ----
    gemm128<<<gemm_blocks, 256>>>(nullptr, Wl2, 1, 0, n);
    gemm128<<<gemm_blocks, 256>>>(nullptr, Wr2, 1, 1, n);
    gat_layer<<<gat_blocks, 256>>>(att2, nullptr, 0, n);  // raw; b2+relu in fc

    // ---- fc ----
    fc_out<<<fc_blocks, 256>>>(Wfc, bfc, b2, out, n);
}